// round 16
// baseline (speedup 1.0000x reference)
#include <cuda_runtime.h>
#include <cstdint>

// Problem constants
#define Dd   480
#define Hh   360
#define Ww   32
#define NPTS 200000
#define DOo  240
#define HOo  180
#define WOo  16
#define NCELLS (DOo*HOo*WOo)        // 691200
#define TABSZ  (Dd*Hh*Ww)           // 5529600
#define POOLED_ELEMS (NCELLS*64)    // 44236800
#define CAP   28672                 // pool per-k bucket capacity (expected ~25k)
#define CAPS  12288                 // subm per-k off-center capacity (expected ~7.2k)
#define FSTRIDE 132                 // Fsm row stride: 16B-aligned rows, fv -> LDS.128

typedef unsigned long long u64;

// ---------------- scratch (static device globals; no allocs allowed) --------
__device__ int   g_table[TABSZ];
__device__ float g_bufA[NPTS*64];
__device__ float g_bufB[NPTS*64];
__device__ float g_bufC[NPTS*64];
// pool
__device__ int   g_kcnt[27];
__device__ int   g_bucket[27*CAP];
__device__ float g_stage[(size_t)27*CAP*64];
__device__ int   g_cellcnt[NCELLS];
__device__ int   g_celllist[NCELLS*8];         // gidx (order nondeterministic)
// subm corrections: buckets 0..8 = pattern31, 9..17 = pattern13
__device__ int   g_kcntS[18];
__device__ int   g_sbucket[18*CAPS];
__device__ float g_stageS[(size_t)18*CAPS*64];
__device__ int   g_pcnt31[NPTS];
__device__ int   g_pcnt13[NPTS];
__device__ int   g_plist31[NPTS*8];
__device__ int   g_plist13[NPTS*8];

// ---------------- packed f32x2 helpers (sm_100+ FFMA2) ----------------------
__device__ __forceinline__ void ffma2(u64 &acc, u64 a, u64 b){
    asm("fma.rn.f32x2 %0, %1, %2, %0;" : "+l"(acc) : "l"(a), "l"(b));
}
__device__ __forceinline__ void fadd2(u64 &acc, u64 v){
    asm("add.rn.f32x2 %0, %0, %1;" : "+l"(acc) : "l"(v));
}
__device__ __forceinline__ u64 dup2(float f){
    u64 r; asm("mov.b64 %0, {%1, %1};" : "=l"(r) : "f"(f)); return r;
}
__device__ __forceinline__ float2 un2(u64 v){
    float2 r; asm("mov.b64 {%0, %1}, %2;" : "=f"(r.x), "=f"(r.y) : "l"(v)); return r;
}

// ---------------- init ------------------------------------------------------
__global__ void k_init(){
    int stride = gridDim.x*blockDim.x;
    int t = blockIdx.x*blockDim.x + threadIdx.x;
    int4 m = make_int4(-1,-1,-1,-1);
    for (int i = t; i < TABSZ/4; i += stride) ((int4*)g_table)[i] = m;
    int4 zz = make_int4(0,0,0,0);
    for (int i = t; i < NCELLS/4; i += stride) ((int4*)g_cellcnt)[i] = zz;
    if (t < 27) g_kcnt[t] = 0;
    if (t < 18) g_kcntS[t] = 0;
}

__global__ void k_build_table(const int* __restrict__ coords){
    int i = blockIdx.x*blockDim.x + threadIdx.x;
    if (i >= NPTS) return;
    int4 c = ((const int4*)coords)[i];   // (b,z,y,x), b==0
    g_table[(c.y*Hh + c.z)*Ww + c.w] = i;
}

// ---------------- merged prep: subm off-center pairs + pool scatter ---------
__global__ void __launch_bounds__(256) k_prep(const int* __restrict__ coords){
    __shared__ int s_cnt[45], s_base[45];   // [0..17] subm, [18..44] pool
    int tid = threadIdx.x;
    if (tid < 45) s_cnt[tid] = 0;
    __syncthreads();
    int i = blockIdx.x*blockDim.x + tid;

    int nh = 0, n31 = 0;
    int hk[16], hq[16], hr[16];
    int np = 0;
    int pk[8], pcell[8], prank[8];

    if (i < NPTS){
        int4 c = ((const int4*)coords)[i];
        int z = c.y, y = c.z, x = c.w;
        #pragma unroll
        for (int k = 0; k < 9; k++){            // pattern 31: (dz,0,dx)
            if (k == 4) continue;
            int dz = k/3 - 1, dx = k%3 - 1;
            int nz = z+dz, nx = x+dx;
            if ((unsigned)nz < Dd && (unsigned)nx < Ww){
                int q = g_table[(nz*Hh + y)*Ww + nx];
                if (q >= 0){ hk[nh]=k; hq[nh]=q; hr[nh]=atomicAdd(&s_cnt[k],1); nh++; }
            }
        }
        n31 = nh;
        #pragma unroll
        for (int k = 0; k < 9; k++){            // pattern 13: (0,dy,dx)
            if (k == 4) continue;
            int dy = k/3 - 1, dx = k%3 - 1;
            int ny = y+dy, nx = x+dx;
            if ((unsigned)ny < Hh && (unsigned)nx < Ww){
                int q = g_table[(z*Hh + ny)*Ww + nx];
                if (q >= 0){ hk[nh]=9+k; hq[nh]=q; hr[nh]=atomicAdd(&s_cnt[9+k],1); nh++; }
            }
        }
        #pragma unroll
        for (int kd=0; kd<3; kd++){
            int oz = z + 1 - kd;
            if (oz & 1) continue;
            oz >>= 1; if ((unsigned)oz >= DOo) continue;
            #pragma unroll
            for (int kh=0; kh<3; kh++){
                int oy = y + 1 - kh;
                if (oy & 1) continue;
                oy >>= 1; if ((unsigned)oy >= HOo) continue;
                #pragma unroll
                for (int kw=0; kw<3; kw++){
                    int ox = x + 1 - kw;
                    if (ox & 1) continue;
                    ox >>= 1; if ((unsigned)ox >= WOo) continue;
                    int k = (kd*3 + kh)*3 + kw;
                    pk[np]    = k;
                    pcell[np] = (oz*HOo + oy)*WOo + ox;
                    prank[np] = atomicAdd(&s_cnt[18 + k], 1);
                    np++;
                }
            }
        }
    }
    __syncthreads();
    if (tid < 18)      s_base[tid] = atomicAdd(&g_kcntS[tid], s_cnt[tid]);
    else if (tid < 45) s_base[tid] = atomicAdd(&g_kcnt[tid-18], s_cnt[tid]);
    __syncthreads();

    if (i < NPTS){
        int c31 = 0, c13 = 0;
        for (int h = 0; h < nh; h++){
            int kk = hk[h];
            int slot = s_base[kk] + hr[h];
            if (slot >= CAPS) continue;          // safety, never expected
            int gidx = kk*CAPS + slot;
            g_sbucket[gidx] = hq[h];
            if (h < n31) g_plist31[i*8 + (c31++)] = gidx;
            else         g_plist13[i*8 + (c13++)] = gidx;
        }
        g_pcnt31[i] = c31;
        g_pcnt13[i] = c13;
        for (int h = 0; h < np; h++){
            int k = pk[h];
            int slot = s_base[18 + k] + prank[h];
            if (slot >= CAP) continue;
            int gidx = k*CAP + slot;
            g_bucket[gidx] = i;
            int s2 = atomicAdd(&g_cellcnt[pcell[h]], 1);
            g_celllist[pcell[h]*8 + s2] = gidx;
        }
    }
}

// ================= shared GEMM building blocks ==============================
// Wsm layout: [ci][cpg*4 + j] u64  -> each thread's 4 pairs = 2x LDS.128
// Fsm layout: [ci][row], stride FSTRIDE=132 -> 8 rows = 2x LDS.128

// stage weights with relayout: src [ci][cp], cp = cpg + 8j -> dst [ci][cpg*4+j]
template<int CIN>
__device__ __forceinline__ void stage_W(u64* Wsm, const u64* Wk, int tid){
    #pragma unroll
    for (int t = tid; t < CIN*32; t += 128){
        int ci = t >> 5, cp = t & 31;
        Wsm[ci*32 + (cp & 7)*4 + (cp >> 3)] = Wk[t];
    }
}

template<int CIN>
__device__ __forceinline__ void gemm_body(
        const u64* __restrict__ Wsm, const float* __restrict__ Fsm,
        int cpg, int rbase, u64 (&acc)[4][8])
{
    #pragma unroll 2
    for (int ci = 0; ci < CIN; ci++){
        const float4* wp = (const float4*)(Wsm + ci*32 + cpg*4);
        float4 w01 = wp[0], w23 = wp[1];
        u64 wv0 = ((const u64*)&w01)[0], wv1 = ((const u64*)&w01)[1];
        u64 wv2 = ((const u64*)&w23)[0], wv3 = ((const u64*)&w23)[1];
        const float4* fp = (const float4*)(Fsm + ci*FSTRIDE + rbase);
        float4 f03 = fp[0], f47 = fp[1];
        float fv[8] = {f03.x, f03.y, f03.z, f03.w, f47.x, f47.y, f47.z, f47.w};
        #pragma unroll
        for (int r = 0; r < 8; r++){
            u64 fb = dup2(fv[r]);
            ffma2(acc[0][r], wv0, fb);
            ffma2(acc[1][r], wv1, fb);
            ffma2(acc[2][r], wv2, fb);
            ffma2(acc[3][r], wv3, fb);
        }
    }
}

// ---------------- subm correction GEMM: dual-input, per-k batched -----------
// grid (CAPS/128, 18), block 128.  stageS[gidx] = in[sbucket[gidx]] @ W[kk%9]
template<int CIN>
__global__ void __launch_bounds__(128) k_corr_gemm(
        const float* __restrict__ inA, const float* __restrict__ WA,
        const float* __restrict__ inB, const float* __restrict__ WB)
{
    extern __shared__ char smraw[];
    u64*   Wsm = (u64*)smraw;                        // CIN*32 u64
    float* Fsm = (float*)(smraw + CIN*32*8);         // CIN x FSTRIDE floats

    int kk   = blockIdx.y;
    int cntk = g_kcntS[kk];
    int row0 = blockIdx.x * 128;
    if (row0 >= cntk) return;
    int nrows = min(128, cntk - row0);

    const float* fin = (kk < 9) ? inA : inB;
    const float* Wg  = (kk < 9) ? WA  : WB;

    int tid  = threadIdx.x;
    int lane = tid & 31;
    int w    = tid >> 5;

    stage_W<CIN>(Wsm, (const u64*)Wg + (size_t)(kk % 9)*CIN*32, tid);

    for (int r = 0; r < 32; r++){
        int row = w*32 + r;
        if (CIN == 64){
            float2 f = make_float2(0.f, 0.f);
            if (row < nrows){
                int p = g_sbucket[kk*CAPS + row0 + row];
                f = ((const float2*)(fin + (size_t)p*64))[lane];
            }
            Fsm[(2*lane  )*FSTRIDE + row] = f.x;
            Fsm[(2*lane+1)*FSTRIDE + row] = f.y;
        } else {
            float f = 0.f;
            if (row < nrows){
                int p = g_sbucket[kk*CAPS + row0 + row];
                f = fin[(size_t)p*32 + lane];
            }
            Fsm[lane*FSTRIDE + row] = f;
        }
    }
    __syncthreads();

    int cpg = lane & 7;
    int rbase = w*32 + (lane >> 3)*8;

    u64 acc[4][8];
    #pragma unroll
    for (int j = 0; j < 4; j++)
        #pragma unroll
        for (int r = 0; r < 8; r++) acc[j][r] = 0ull;

    gemm_body<CIN>(Wsm, Fsm, cpg, rbase, acc);

    #pragma unroll
    for (int r = 0; r < 8; r++){
        int row = rbase + r;
        if (row < nrows){
            u64* dst = (u64*)g_stageS + (size_t)(kk*CAPS + row0 + row)*32;
            #pragma unroll
            for (int j = 0; j < 4; j++) dst[cpg + 8*j] = acc[j][r];
        }
    }
}

// ---------------- subm dense-center GEMM + correction sum + leaky -----------
// grid ceil(NPTS/128), block 128. out[p] = leaky(fin[p]@W[4] + sum stageS) [+res]
template<int CIN, bool FUSE>
__global__ void __launch_bounds__(128) k_dense(
        const float* __restrict__ fin, const float* __restrict__ Wg,
        const int* __restrict__ pcnt,  const int* __restrict__ plist,
        const float* __restrict__ res, float* __restrict__ fout)
{
    extern __shared__ char smraw[];
    u64*   Wsm = (u64*)smraw;
    float* Fsm = (float*)(smraw + CIN*32*8);

    int row0  = blockIdx.x * 128;
    int nrows = min(128, NPTS - row0);

    int tid  = threadIdx.x;
    int lane = tid & 31;
    int w    = tid >> 5;

    stage_W<CIN>(Wsm, (const u64*)Wg + (size_t)4*CIN*32, tid);   // center tap

    for (int r = 0; r < 32; r++){
        int row = w*32 + r;
        if (CIN == 64){
            float2 f = make_float2(0.f, 0.f);
            if (row < nrows)
                f = ((const float2*)(fin + (size_t)(row0+row)*64))[lane];
            Fsm[(2*lane  )*FSTRIDE + row] = f.x;
            Fsm[(2*lane+1)*FSTRIDE + row] = f.y;
        } else {
            float f = 0.f;
            if (row < nrows)
                f = fin[(size_t)(row0+row)*32 + lane];
            Fsm[lane*FSTRIDE + row] = f;
        }
    }
    __syncthreads();

    int cpg = lane & 7;
    int rbase = w*32 + (lane >> 3)*8;

    u64 acc[4][8];
    #pragma unroll
    for (int j = 0; j < 4; j++)
        #pragma unroll
        for (int r = 0; r < 8; r++) acc[j][r] = 0ull;

    gemm_body<CIN>(Wsm, Fsm, cpg, rbase, acc);

    // corrections (ascending k) + leaky + residual + store
    #pragma unroll
    for (int r = 0; r < 8; r++){
        int row = rbase + r;
        if (row >= nrows) continue;
        int grow = row0 + row;
        int cn = pcnt[grow];
        for (int j = 0; j < cn; j++){
            int gidx = plist[grow*8 + j];
            const u64* srow = (const u64*)g_stageS + (size_t)gidx*32;
            fadd2(acc[0][r], srow[cpg      ]);
            fadd2(acc[1][r], srow[cpg + 8  ]);
            fadd2(acc[2][r], srow[cpg + 16 ]);
            fadd2(acc[3][r], srow[cpg + 24 ]);
        }
        #pragma unroll
        for (int jj = 0; jj < 4; jj++){
            float2 a = un2(acc[jj][r]);
            a.x = a.x > 0.f ? a.x : 0.01f*a.x;
            a.y = a.y > 0.f ? a.y : 0.01f*a.y;
            if (FUSE){
                float2 rv = ((const float2*)(res + (size_t)grow*64))[cpg + 8*jj];
                a.x += rv.x; a.y += rv.y;
            }
            ((float2*)(fout + (size_t)grow*64))[cpg + 8*jj] = a;
        }
    }
}

// ---------------- pool Phase A: per-k batched GEMM into staging -------------
__global__ void __launch_bounds__(128) k_pool_gemm(
        const float* __restrict__ rA, const float* __restrict__ Wg)
{
    extern __shared__ char smraw[];
    u64*   Wsm = (u64*)smraw;                    // 64ci x 32cp u64 = 16384 B
    float* Fsm = (float*)(smraw + 16384);        // 64ci x FSTRIDE floats

    int k    = blockIdx.y;
    int cntk = g_kcnt[k];
    int row0 = blockIdx.x * 128;
    if (row0 >= cntk) return;
    int nrows = min(128, cntk - row0);

    int tid  = threadIdx.x;
    int lane = tid & 31;
    int w    = tid >> 5;

    stage_W<64>(Wsm, (const u64*)Wg + (size_t)k*2048, tid);

    for (int r = 0; r < 32; r++){
        int row = w*32 + r;
        float2 f = make_float2(0.f, 0.f);
        if (row < nrows){
            int p = g_bucket[k*CAP + row0 + row];
            f = ((const float2*)(rA + (size_t)p*64))[lane];
        }
        Fsm[(2*lane  )*FSTRIDE + row] = f.x;
        Fsm[(2*lane+1)*FSTRIDE + row] = f.y;
    }
    __syncthreads();

    int cpg = lane & 7;
    int rbase = w*32 + (lane >> 3)*8;

    u64 acc[4][8];
    #pragma unroll
    for (int j = 0; j < 4; j++)
        #pragma unroll
        for (int r = 0; r < 8; r++) acc[j][r] = 0ull;

    gemm_body<64>(Wsm, Fsm, cpg, rbase, acc);

    #pragma unroll
    for (int r = 0; r < 8; r++){
        int row = rbase + r;
        if (row < nrows){
            u64* dst = (u64*)g_stage + (size_t)(k*CAP + row0 + row)*32;
            #pragma unroll
            for (int j = 0; j < 4; j++) dst[cpg + 8*j] = acc[j][r];
        }
    }
}

// ---------------- pool Phase B: per-cell sum (arrival order) ----------------
__global__ void __launch_bounds__(256) k_pool_sum(float* __restrict__ outp){
    int cell = blockIdx.x*8 + (threadIdx.x >> 5);
    int lane = threadIdx.x & 31;
    if (cell >= NCELLS) return;
    int cnt = g_cellcnt[cell];
    int gidx = 0;
    if (lane < cnt) gidx = g_celllist[cell*8 + lane];
    u64 acc = 0ull;
    for (int j = 0; j < cnt; j++){
        int g = __shfl_sync(0xffffffffu, gidx, j);
        u64 v = ((const u64*)g_stage)[(size_t)g*32 + lane];
        fadd2(acc, v);
    }
    ((u64*)outp)[(size_t)cell*32 + lane] = acc;
}

// ---------------- launch ----------------------------------------------------
extern "C" void kernel_launch(void* const* d_in, const int* in_sizes, int n_in,
                              void* d_out, int out_size)
{
    const float* feats  = (const float*)d_in[0];
    const int*   coords = (const int*)  d_in[1];
    const float* W1     = (const float*)d_in[2];
    const float* W1_2   = (const float*)d_in[3];
    const float* W2     = (const float*)d_in[4];
    const float* W3     = (const float*)d_in[5];
    const float* Wpool  = (const float*)d_in[6];

    float* out    = (float*)d_out;
    float* pooled = out;                         // (1,240,180,16,64)
    float* rA_out = out + POOLED_ELEMS;          // (200000,64)

    float *bufA, *bufB, *bufC;
    int *pc31, *pc13, *pl31, *pl13;
    cudaGetSymbolAddress((void**)&bufA, g_bufA);
    cudaGetSymbolAddress((void**)&bufB, g_bufB);
    cudaGetSymbolAddress((void**)&bufC, g_bufC);
    cudaGetSymbolAddress((void**)&pc31, g_pcnt31);
    cudaGetSymbolAddress((void**)&pc13, g_pcnt13);
    cudaGetSymbolAddress((void**)&pl31, g_plist31);
    cudaGetSymbolAddress((void**)&pl13, g_plist13);

    // smem sizes: W (CIN*32*8 B) + Fsm (CIN*FSTRIDE*4 B)
    const int SM32 = 32*32*8 + 32*FSTRIDE*4;   // 8192 + 16896 = 25088
    const int SM64 = 64*32*8 + 64*FSTRIDE*4;   // 16384 + 33792 = 50176
    cudaFuncSetAttribute(k_corr_gemm<32>,  cudaFuncAttributeMaxDynamicSharedMemorySize, SM32);
    cudaFuncSetAttribute(k_corr_gemm<64>,  cudaFuncAttributeMaxDynamicSharedMemorySize, SM64);
    cudaFuncSetAttribute(k_dense<32,false>,cudaFuncAttributeMaxDynamicSharedMemorySize, SM32);
    cudaFuncSetAttribute(k_dense<64,false>,cudaFuncAttributeMaxDynamicSharedMemorySize, SM64);
    cudaFuncSetAttribute(k_dense<64,true>, cudaFuncAttributeMaxDynamicSharedMemorySize, SM64);
    cudaFuncSetAttribute(k_pool_gemm,      cudaFuncAttributeMaxDynamicSharedMemorySize, SM64);

    k_init<<<1024, 256>>>();
    k_build_table<<<(NPTS+255)/256, 256>>>(coords);
    k_prep<<<(NPTS+255)/256, 256>>>(coords);

    const int DGRID = (NPTS + 127)/128;
    dim3 gC(CAPS/128, 18);

    // Stage 1 corrections: buckets 0..8 = feats@W1 (pattern31, for L1),
    //                      buckets 9..17 = feats@W2 (pattern13, for L3)
    k_corr_gemm<32><<<gC, 128, SM32>>>(feats, W1, feats, W2);
    // L1: sc1 = leaky(subm(feats, W1, OFF_31))      -> bufA
    k_dense<32,false><<<DGRID, 128, SM32>>>(feats, W1, pc31, pl31, nullptr, bufA);
    // L3: rA1 = leaky(subm(feats, W2, OFF_13))      -> bufB
    k_dense<32,false><<<DGRID, 128, SM32>>>(feats, W2, pc13, pl13, nullptr, bufB);
    // Stage 2 corrections: buckets 0..8 = bufB@W3 (pattern31, for L4),
    //                      buckets 9..17 = bufA@W1_2 (pattern13, for L2)
    k_corr_gemm<64><<<gC, 128, SM64>>>(bufB, W3, bufA, W1_2);
    // L2: sc = leaky(subm(bufA, W1_2, OFF_13))      -> bufC
    k_dense<64,false><<<DGRID, 128, SM64>>>(bufA, W1_2, pc13, pl13, nullptr, bufC);
    // L4: rA = leaky(subm(bufB, W3, OFF_31)) + bufC -> rA_out
    k_dense<64,true ><<<DGRID, 128, SM64>>>(bufB, W3, pc31, pl31, bufC, rA_out);

    // pool: Phase A (k-batched GEMM to staging), Phase B (per-cell sum)
    dim3 gA(CAP/128, 27);
    k_pool_gemm<<<gA, 128, SM64>>>(rA_out, Wpool);
    k_pool_sum<<<(NCELLS+7)/8, 256>>>(pooled);
}

// round 17
// speedup vs baseline: 1.1905x; 1.1905x over previous
#include <cuda_runtime.h>
#include <cstdint>

// Problem constants
#define Dd   480
#define Hh   360
#define Ww   32
#define NPTS 200000
#define DOo  240
#define HOo  180
#define WOo  16
#define NCELLS (DOo*HOo*WOo)        // 691200
#define TABSZ  (Dd*Hh*Ww)           // 5529600
#define POOLED_ELEMS (NCELLS*64)    // 44236800
#define CAP   28672                 // pool per-k bucket capacity (expected ~25k)
#define CAPS  12288                 // subm per-k off-center capacity (expected ~7.2k)

typedef unsigned long long u64;

// ---------------- scratch (static device globals; no allocs allowed) --------
__device__ int   g_table[TABSZ];
__device__ float g_bufA[NPTS*64];
__device__ float g_bufB[NPTS*64];
__device__ float g_bufC[NPTS*64];
// pool
__device__ int   g_kcnt[27];
__device__ int   g_bucket[27*CAP];
__device__ float g_stage[(size_t)27*CAP*64];
__device__ int   g_cellcnt[NCELLS];
__device__ int   g_celllist[NCELLS*8];         // gidx (order nondeterministic)
// subm corrections: buckets 0..8 = pattern31, 9..17 = pattern13
// Two staging regions (A = chain1: L1/L2, B = chain2: L3/L4) so the chains
// can run concurrently on separate streams without racing.
__device__ int   g_kcntS[18];
__device__ int   g_sbucket[18*CAPS];
__device__ float g_stageS_A[(size_t)18*CAPS*64];
__device__ float g_stageS_B[(size_t)18*CAPS*64];
__device__ int   g_pcnt31[NPTS];
__device__ int   g_pcnt13[NPTS];
__device__ int   g_plist31[NPTS*8];
__device__ int   g_plist13[NPTS*8];

// ---------------- packed f32x2 helpers (sm_100+ FFMA2) ----------------------
__device__ __forceinline__ void ffma2(u64 &acc, u64 a, u64 b){
    asm("fma.rn.f32x2 %0, %1, %2, %0;" : "+l"(acc) : "l"(a), "l"(b));
}
__device__ __forceinline__ void fadd2(u64 &acc, u64 v){
    asm("add.rn.f32x2 %0, %0, %1;" : "+l"(acc) : "l"(v));
}
__device__ __forceinline__ u64 dup2(float f){
    u64 r; asm("mov.b64 %0, {%1, %1};" : "=l"(r) : "f"(f)); return r;
}
__device__ __forceinline__ float2 un2(u64 v){
    float2 r; asm("mov.b64 {%0, %1}, %2;" : "=f"(r.x), "=f"(r.y) : "l"(v)); return r;
}

// ---------------- init ------------------------------------------------------
__global__ void k_init(){
    int stride = gridDim.x*blockDim.x;
    int t = blockIdx.x*blockDim.x + threadIdx.x;
    int4 m = make_int4(-1,-1,-1,-1);
    for (int i = t; i < TABSZ/4; i += stride) ((int4*)g_table)[i] = m;
    int4 zz = make_int4(0,0,0,0);
    for (int i = t; i < NCELLS/4; i += stride) ((int4*)g_cellcnt)[i] = zz;
    if (t < 27) g_kcnt[t] = 0;
    if (t < 18) g_kcntS[t] = 0;
}

__global__ void k_build_table(const int* __restrict__ coords){
    int i = blockIdx.x*blockDim.x + threadIdx.x;
    if (i >= NPTS) return;
    int4 c = ((const int4*)coords)[i];   // (b,z,y,x), b==0
    g_table[(c.y*Hh + c.z)*Ww + c.w] = i;
}

// ---------------- merged prep: subm off-center pairs + pool scatter ---------
__global__ void __launch_bounds__(256) k_prep(const int* __restrict__ coords){
    __shared__ int s_cnt[45], s_base[45];   // [0..17] subm, [18..44] pool
    int tid = threadIdx.x;
    if (tid < 45) s_cnt[tid] = 0;
    __syncthreads();
    int i = blockIdx.x*blockDim.x + tid;

    int nh = 0, n31 = 0;
    int hk[16], hq[16], hr[16];
    int np = 0;
    int pk[8], pcell[8], prank[8];

    if (i < NPTS){
        int4 c = ((const int4*)coords)[i];
        int z = c.y, y = c.z, x = c.w;
        #pragma unroll
        for (int k = 0; k < 9; k++){            // pattern 31: (dz,0,dx)
            if (k == 4) continue;
            int dz = k/3 - 1, dx = k%3 - 1;
            int nz = z+dz, nx = x+dx;
            if ((unsigned)nz < Dd && (unsigned)nx < Ww){
                int q = g_table[(nz*Hh + y)*Ww + nx];
                if (q >= 0){ hk[nh]=k; hq[nh]=q; hr[nh]=atomicAdd(&s_cnt[k],1); nh++; }
            }
        }
        n31 = nh;
        #pragma unroll
        for (int k = 0; k < 9; k++){            // pattern 13: (0,dy,dx)
            if (k == 4) continue;
            int dy = k/3 - 1, dx = k%3 - 1;
            int ny = y+dy, nx = x+dx;
            if ((unsigned)ny < Hh && (unsigned)nx < Ww){
                int q = g_table[(z*Hh + ny)*Ww + nx];
                if (q >= 0){ hk[nh]=9+k; hq[nh]=q; hr[nh]=atomicAdd(&s_cnt[9+k],1); nh++; }
            }
        }
        #pragma unroll
        for (int kd=0; kd<3; kd++){
            int oz = z + 1 - kd;
            if (oz & 1) continue;
            oz >>= 1; if ((unsigned)oz >= DOo) continue;
            #pragma unroll
            for (int kh=0; kh<3; kh++){
                int oy = y + 1 - kh;
                if (oy & 1) continue;
                oy >>= 1; if ((unsigned)oy >= HOo) continue;
                #pragma unroll
                for (int kw=0; kw<3; kw++){
                    int ox = x + 1 - kw;
                    if (ox & 1) continue;
                    ox >>= 1; if ((unsigned)ox >= WOo) continue;
                    int k = (kd*3 + kh)*3 + kw;
                    pk[np]    = k;
                    pcell[np] = (oz*HOo + oy)*WOo + ox;
                    prank[np] = atomicAdd(&s_cnt[18 + k], 1);
                    np++;
                }
            }
        }
    }
    __syncthreads();
    if (tid < 18)      s_base[tid] = atomicAdd(&g_kcntS[tid], s_cnt[tid]);
    else if (tid < 45) s_base[tid] = atomicAdd(&g_kcnt[tid-18], s_cnt[tid]);
    __syncthreads();

    if (i < NPTS){
        int c31 = 0, c13 = 0;
        for (int h = 0; h < nh; h++){
            int kk = hk[h];
            int slot = s_base[kk] + hr[h];
            if (slot >= CAPS) continue;          // safety, never expected
            int gidx = kk*CAPS + slot;
            g_sbucket[gidx] = hq[h];
            if (h < n31) g_plist31[i*8 + (c31++)] = gidx;
            else         g_plist13[i*8 + (c13++)] = gidx;
        }
        g_pcnt31[i] = c31;
        g_pcnt13[i] = c13;
        for (int h = 0; h < np; h++){
            int k = pk[h];
            int slot = s_base[18 + k] + prank[h];
            if (slot >= CAP) continue;
            int gidx = k*CAP + slot;
            g_bucket[gidx] = i;
            int s2 = atomicAdd(&g_cellcnt[pcell[h]], 1);
            g_celllist[pcell[h]*8 + s2] = gidx;
        }
    }
}

// ---------------- subm correction GEMM: per-k batched, staged ---------------
// grid (CAPS/128, 9), block 128.  stageS[gidx] = fin[sbucket[gidx]] @ W[k]
template<int CIN>
__global__ void __launch_bounds__(128) k_corr_gemm(
        const float* __restrict__ fin, const float* __restrict__ Wg,
        float* __restrict__ stageS, int kbase)
{
    extern __shared__ char smraw[];
    u64*   Wsm = (u64*)smraw;                        // CIN*32 u64
    float* Fsm = (float*)(smraw + CIN*32*8);         // CIN x 129 floats

    int kk   = kbase + blockIdx.y;
    int cntk = g_kcntS[kk];
    int row0 = blockIdx.x * 128;
    if (row0 >= cntk) return;
    int nrows = min(128, cntk - row0);

    int tid  = threadIdx.x;
    int lane = tid & 31;
    int w    = tid >> 5;

    const u64* Wk = (const u64*)Wg + (size_t)blockIdx.y*CIN*32;
    #pragma unroll
    for (int j = 0; j < CIN/4; j++)
        Wsm[tid + j*128] = Wk[tid + j*128];

    for (int r = 0; r < 32; r++){
        int row = w*32 + r;
        if (CIN == 64){
            float2 f = make_float2(0.f, 0.f);
            if (row < nrows){
                int p = g_sbucket[kk*CAPS + row0 + row];
                f = ((const float2*)(fin + (size_t)p*64))[lane];
            }
            Fsm[(2*lane  )*129 + row] = f.x;
            Fsm[(2*lane+1)*129 + row] = f.y;
        } else {
            float f = 0.f;
            if (row < nrows){
                int p = g_sbucket[kk*CAPS + row0 + row];
                f = fin[(size_t)p*32 + lane];
            }
            Fsm[lane*129 + row] = f;
        }
    }
    __syncthreads();

    int cpg = lane & 7;
    int rg  = lane >> 3;
    int rbase = w*32 + rg*8;

    u64 acc[4][8];
    #pragma unroll
    for (int j = 0; j < 4; j++)
        #pragma unroll
        for (int r = 0; r < 8; r++) acc[j][r] = 0ull;

    #pragma unroll 2
    for (int ci = 0; ci < CIN; ci++){
        u64 wv[4];
        #pragma unroll
        for (int j = 0; j < 4; j++) wv[j] = Wsm[ci*32 + cpg + 8*j];
        float fv[8];
        #pragma unroll
        for (int r = 0; r < 8; r++) fv[r] = Fsm[ci*129 + rbase + r];
        #pragma unroll
        for (int r = 0; r < 8; r++){
            u64 fb = dup2(fv[r]);
            ffma2(acc[0][r], wv[0], fb);
            ffma2(acc[1][r], wv[1], fb);
            ffma2(acc[2][r], wv[2], fb);
            ffma2(acc[3][r], wv[3], fb);
        }
    }

    #pragma unroll
    for (int r = 0; r < 8; r++){
        int row = rbase + r;
        if (row < nrows){
            u64* dst = (u64*)stageS + (size_t)(kk*CAPS + row0 + row)*32;
            #pragma unroll
            for (int j = 0; j < 4; j++) dst[cpg + 8*j] = acc[j][r];
        }
    }
}

// ---------------- subm dense-center GEMM + correction sum + leaky -----------
// grid ceil(NPTS/128), block 128. out[p] = leaky(fin[p]@W[4] + sum stageS) [+res]
template<int CIN, bool FUSE>
__global__ void __launch_bounds__(128) k_dense(
        const float* __restrict__ fin, const float* __restrict__ Wg,
        const int* __restrict__ pcnt,  const int* __restrict__ plist,
        const float* __restrict__ stageS,
        const float* __restrict__ res, float* __restrict__ fout)
{
    extern __shared__ char smraw[];
    u64*   Wsm = (u64*)smraw;                        // CIN*32 u64
    float* Fsm = (float*)(smraw + CIN*32*8);         // CIN x 129 floats

    int row0  = blockIdx.x * 128;
    int nrows = min(128, NPTS - row0);

    int tid  = threadIdx.x;
    int lane = tid & 31;
    int w    = tid >> 5;

    const u64* Wc = (const u64*)Wg + (size_t)4*CIN*32;   // center tap
    #pragma unroll
    for (int j = 0; j < CIN/4; j++)
        Wsm[tid + j*128] = Wc[tid + j*128];

    for (int r = 0; r < 32; r++){
        int row = w*32 + r;
        if (CIN == 64){
            float2 f = make_float2(0.f, 0.f);
            if (row < nrows)
                f = ((const float2*)(fin + (size_t)(row0+row)*64))[lane];
            Fsm[(2*lane  )*129 + row] = f.x;
            Fsm[(2*lane+1)*129 + row] = f.y;
        } else {
            float f = 0.f;
            if (row < nrows)
                f = fin[(size_t)(row0+row)*32 + lane];
            Fsm[lane*129 + row] = f;
        }
    }
    __syncthreads();

    int cpg = lane & 7;
    int rg  = lane >> 3;
    int rbase = w*32 + rg*8;

    u64 acc[4][8];
    #pragma unroll
    for (int j = 0; j < 4; j++)
        #pragma unroll
        for (int r = 0; r < 8; r++) acc[j][r] = 0ull;

    #pragma unroll 2
    for (int ci = 0; ci < CIN; ci++){
        u64 wv[4];
        #pragma unroll
        for (int j = 0; j < 4; j++) wv[j] = Wsm[ci*32 + cpg + 8*j];
        float fv[8];
        #pragma unroll
        for (int r = 0; r < 8; r++) fv[r] = Fsm[ci*129 + rbase + r];
        #pragma unroll
        for (int r = 0; r < 8; r++){
            u64 fb = dup2(fv[r]);
            ffma2(acc[0][r], wv[0], fb);
            ffma2(acc[1][r], wv[1], fb);
            ffma2(acc[2][r], wv[2], fb);
            ffma2(acc[3][r], wv[3], fb);
        }
    }

    // corrections (ascending k) + leaky + residual + store
    #pragma unroll
    for (int r = 0; r < 8; r++){
        int row = rbase + r;
        if (row >= nrows) continue;
        int grow = row0 + row;
        int cn = pcnt[grow];
        for (int j = 0; j < cn; j++){
            int gidx = plist[grow*8 + j];
            const u64* srow = (const u64*)stageS + (size_t)gidx*32;
            fadd2(acc[0][r], srow[cpg      ]);
            fadd2(acc[1][r], srow[cpg + 8  ]);
            fadd2(acc[2][r], srow[cpg + 16 ]);
            fadd2(acc[3][r], srow[cpg + 24 ]);
        }
        #pragma unroll
        for (int jj = 0; jj < 4; jj++){
            float2 a = un2(acc[jj][r]);
            a.x = a.x > 0.f ? a.x : 0.01f*a.x;
            a.y = a.y > 0.f ? a.y : 0.01f*a.y;
            if (FUSE){
                float2 rv = ((const float2*)(res + (size_t)grow*64))[cpg + 8*jj];
                a.x += rv.x; a.y += rv.y;
            }
            ((float2*)(fout + (size_t)grow*64))[cpg + 8*jj] = a;
        }
    }
}

// ---------------- pool Phase A: per-k batched GEMM into staging -------------
__global__ void __launch_bounds__(128) k_pool_gemm(
        const float* __restrict__ rA, const float* __restrict__ Wg)
{
    extern __shared__ char smraw[];
    u64*   Wsm = (u64*)smraw;                    // 64ci x 32cp u64 = 16384 B
    float* Fsm = (float*)(smraw + 16384);        // 64ci x 129 floats

    int k    = blockIdx.y;
    int cntk = g_kcnt[k];
    int row0 = blockIdx.x * 128;
    if (row0 >= cntk) return;
    int nrows = min(128, cntk - row0);

    int tid  = threadIdx.x;
    int lane = tid & 31;
    int w    = tid >> 5;

    const u64* Wg64 = (const u64*)Wg + (size_t)k*2048;
    #pragma unroll
    for (int j = 0; j < 16; j++)
        Wsm[tid + j*128] = Wg64[tid + j*128];

    for (int r = 0; r < 32; r++){
        int row = w*32 + r;
        float2 f = make_float2(0.f, 0.f);
        if (row < nrows){
            int p = g_bucket[k*CAP + row0 + row];
            f = ((const float2*)(rA + (size_t)p*64))[lane];
        }
        Fsm[(2*lane  )*129 + row] = f.x;
        Fsm[(2*lane+1)*129 + row] = f.y;
    }
    __syncthreads();

    int cpg = lane & 7;
    int rg  = lane >> 3;
    int rbase = w*32 + rg*8;

    u64 acc[4][8];
    #pragma unroll
    for (int j = 0; j < 4; j++)
        #pragma unroll
        for (int r = 0; r < 8; r++) acc[j][r] = 0ull;

    #pragma unroll 2
    for (int ci = 0; ci < 64; ci++){
        u64 wv[4];
        #pragma unroll
        for (int j = 0; j < 4; j++) wv[j] = Wsm[ci*32 + cpg + 8*j];
        float fv[8];
        #pragma unroll
        for (int r = 0; r < 8; r++) fv[r] = Fsm[ci*129 + rbase + r];
        #pragma unroll
        for (int r = 0; r < 8; r++){
            u64 fb = dup2(fv[r]);
            ffma2(acc[0][r], wv[0], fb);
            ffma2(acc[1][r], wv[1], fb);
            ffma2(acc[2][r], wv[2], fb);
            ffma2(acc[3][r], wv[3], fb);
        }
    }

    #pragma unroll
    for (int r = 0; r < 8; r++){
        int row = rbase + r;
        if (row < nrows){
            u64* dst = (u64*)g_stage + (size_t)(k*CAP + row0 + row)*32;
            #pragma unroll
            for (int j = 0; j < 4; j++) dst[cpg + 8*j] = acc[j][r];
        }
    }
}

// ---------------- pool Phase B: per-cell sum (arrival order) ----------------
__global__ void __launch_bounds__(256) k_pool_sum(float* __restrict__ outp){
    int cell = blockIdx.x*8 + (threadIdx.x >> 5);
    int lane = threadIdx.x & 31;
    if (cell >= NCELLS) return;
    int cnt = g_cellcnt[cell];
    int gidx = 0;
    if (lane < cnt) gidx = g_celllist[cell*8 + lane];
    u64 acc = 0ull;
    for (int j = 0; j < cnt; j++){
        int g = __shfl_sync(0xffffffffu, gidx, j);
        u64 v = ((const u64*)g_stage)[(size_t)g*32 + lane];
        fadd2(acc, v);
    }
    ((u64*)outp)[(size_t)cell*32 + lane] = acc;
}

// ---------------- launch ----------------------------------------------------
extern "C" void kernel_launch(void* const* d_in, const int* in_sizes, int n_in,
                              void* d_out, int out_size)
{
    const float* feats  = (const float*)d_in[0];
    const int*   coords = (const int*)  d_in[1];
    const float* W1     = (const float*)d_in[2];
    const float* W1_2   = (const float*)d_in[3];
    const float* W2     = (const float*)d_in[4];
    const float* W3     = (const float*)d_in[5];
    const float* Wpool  = (const float*)d_in[6];

    float* out    = (float*)d_out;
    float* pooled = out;                         // (1,240,180,16,64)
    float* rA_out = out + POOLED_ELEMS;          // (200000,64)

    float *bufA, *bufB, *bufC, *stA, *stB;
    int *pc31, *pc13, *pl31, *pl13;
    cudaGetSymbolAddress((void**)&bufA, g_bufA);
    cudaGetSymbolAddress((void**)&bufB, g_bufB);
    cudaGetSymbolAddress((void**)&bufC, g_bufC);
    cudaGetSymbolAddress((void**)&stA,  g_stageS_A);
    cudaGetSymbolAddress((void**)&stB,  g_stageS_B);
    cudaGetSymbolAddress((void**)&pc31, g_pcnt31);
    cudaGetSymbolAddress((void**)&pc13, g_pcnt13);
    cudaGetSymbolAddress((void**)&pl31, g_plist31);
    cudaGetSymbolAddress((void**)&pl13, g_plist13);

    // lazily-created side streams/events (host objects only; no device allocs)
    static cudaStream_t st1 = nullptr, st2 = nullptr;
    static cudaEvent_t  evH = nullptr, ev1 = nullptr, ev2 = nullptr;
    if (!st1){
        cudaStreamCreateWithFlags(&st1, cudaStreamNonBlocking);
        cudaStreamCreateWithFlags(&st2, cudaStreamNonBlocking);
        cudaEventCreateWithFlags(&evH, cudaEventDisableTiming);
        cudaEventCreateWithFlags(&ev1, cudaEventDisableTiming);
        cudaEventCreateWithFlags(&ev2, cudaEventDisableTiming);
    }

    // smem sizes: W (CIN*32*8 B) + Fsm (CIN*129*4 B)
    const int SM32 = 32*32*8 + 32*129*4;   // 24704
    const int SM64 = 64*32*8 + 64*129*4;   // 49408
    cudaFuncSetAttribute(k_corr_gemm<32>,  cudaFuncAttributeMaxDynamicSharedMemorySize, SM32);
    cudaFuncSetAttribute(k_corr_gemm<64>,  cudaFuncAttributeMaxDynamicSharedMemorySize, SM64);
    cudaFuncSetAttribute(k_dense<32,false>,cudaFuncAttributeMaxDynamicSharedMemorySize, SM32);
    cudaFuncSetAttribute(k_dense<64,false>,cudaFuncAttributeMaxDynamicSharedMemorySize, SM64);
    cudaFuncSetAttribute(k_dense<64,true>, cudaFuncAttributeMaxDynamicSharedMemorySize, SM64);
    cudaFuncSetAttribute(k_pool_gemm,      cudaFuncAttributeMaxDynamicSharedMemorySize, SM64);

    // head (default stream)
    k_init<<<1024, 256>>>();
    k_build_table<<<(NPTS+255)/256, 256>>>(coords);
    k_prep<<<(NPTS+255)/256, 256>>>(coords);
    cudaEventRecord(evH, 0);
    cudaStreamWaitEvent(st1, evH, 0);
    cudaStreamWaitEvent(st2, evH, 0);

    const int DGRID = (NPTS + 127)/128;
    dim3 gC(CAPS/128, 9);

    // ---- chain 1 (stream st1): L1 -> L2, staging region A ----
    // corr: feats@W1 (pattern31, buckets 0..8)
    k_corr_gemm<32><<<gC, 128, SM32, st1>>>(feats, W1, stA, 0);
    // L1: sc1 = leaky(subm(feats, W1, OFF_31))      -> bufA
    k_dense<32,false><<<DGRID, 128, SM32, st1>>>(feats, W1, pc31, pl31, stA, nullptr, bufA);
    // corr: bufA@W1_2 (pattern13, buckets 9..17)
    k_corr_gemm<64><<<gC, 128, SM64, st1>>>(bufA, W1_2, stA, 9);
    // L2: sc = leaky(subm(bufA, W1_2, OFF_13))      -> bufC
    k_dense<64,false><<<DGRID, 128, SM64, st1>>>(bufA, W1_2, pc13, pl13, stA, nullptr, bufC);
    cudaEventRecord(ev1, st1);

    // ---- chain 2 (stream st2): L3 -> corr(W3), staging region B ----
    // corr: feats@W2 (pattern13, buckets 9..17)
    k_corr_gemm<32><<<gC, 128, SM32, st2>>>(feats, W2, stB, 9);
    // L3: rA1 = leaky(subm(feats, W2, OFF_13))      -> bufB
    k_dense<32,false><<<DGRID, 128, SM32, st2>>>(feats, W2, pc13, pl13, stB, nullptr, bufB);
    // corr: bufB@W3 (pattern31, buckets 0..8)
    k_corr_gemm<64><<<gC, 128, SM64, st2>>>(bufB, W3, stB, 0);
    cudaEventRecord(ev2, st2);

    // ---- join on default stream ----
    cudaStreamWaitEvent(0, ev1, 0);
    cudaStreamWaitEvent(0, ev2, 0);

    // L4: rA = leaky(subm(bufB, W3, OFF_31)) + bufC -> rA_out
    k_dense<64,true ><<<DGRID, 128, SM64>>>(bufB, W3, pc31, pl31, stB, bufC, rA_out);

    // pool: Phase A (k-batched GEMM to staging), Phase B (per-cell sum)
    dim3 gA(CAP/128, 27);
    k_pool_gemm<<<gA, 128, SM64>>>(rA_out, Wpool);
    k_pool_sum<<<(NCELLS+7)/8, 256>>>(pooled);
}